// round 1
// baseline (speedup 1.0000x reference)
#include <cuda_runtime.h>

#define B_ 128
#define T_ 4096
#define I_ 64
#define H_ 128
#define G_ 384   /* 3*H */
#define C_ 2
#define ALPHA_ 0.3f
#define BETA_  0.5f

// Scratch (device globals: allocation-free per harness rules)
__device__ float g_x2[(long)B_ * T_ * I_];   // 134 MB: EMA(EMA(x))
__device__ float g_xp[(long)B_ * T_ * G_];   // 805 MB: x2 @ W_ih^T + b_ih
__device__ float g_st11[B_ * C_];
__device__ float g_st12[B_ * C_];

__device__ __forceinline__ float sigm_(float x) {
    x = fminf(fmaxf(x, -30.f), 30.f);
    return 1.f / (1.f + __expf(-x));
}
__device__ __forceinline__ float tanh_(float x) {
    x = fminf(fmaxf(x, -15.f), 15.f);
    float e = __expf(-2.f * x);
    return (1.f - e) / (1.f + e);
}

// ---------------------------------------------------------------------------
// Kernel 1: chained EMAs over time, per (b, i). Also captures st11/st12.
// grid 256, block 32: blockIdx -> (b, half of i), coalesced over i.
// ---------------------------------------------------------------------------
__global__ void ema_kernel(const float* __restrict__ x) {
    int b = blockIdx.x >> 1;
    int i = ((blockIdx.x & 1) << 5) + threadIdx.x;
    const float* xin = x + (long)b * T_ * I_ + i;
    float* o = g_x2 + (long)b * T_ * I_ + i;

    float x1 = xin[0];
    float x2 = x1;
    o[0] = x2;
#pragma unroll 4
    for (int t = 1; t < T_; ++t) {
        float xt = xin[(long)t * I_];
        x1 = (1.f - ALPHA_) * xt + ALPHA_ * x1;
        x2 = (1.f - BETA_) * x1 + BETA_ * x2;
        o[(long)t * I_] = x2;
    }
    if (i == 1 || i == 2) {
        g_st11[b * C_ + (i - 1)] = x1;
        g_st12[b * C_ + (i - 1)] = x2;
    }
}

// ---------------------------------------------------------------------------
// Kernel 2: xp[m, g] = b_ih[g] + sum_k x2[m, k] * W_ih[g, k]
// m = b*T + t (524288 rows). One CTA = 64 rows x 384 cols.
// W_ih row per thread in registers; x2 tile in smem (broadcast reads).
// ---------------------------------------------------------------------------
__global__ __launch_bounds__(384) void xp_gemm_kernel(
    const float* __restrict__ W_ih, const float* __restrict__ b_ih) {
    __shared__ float xs[64 * I_];  // 16 KB, identical layout to g_x2 slice
    int m0 = blockIdx.x * 64;
    int g = threadIdx.x;

    // cooperative vectorized tile load (contiguous)
    {
        const float4* src = (const float4*)(g_x2 + (long)m0 * I_);
        float4* dst = (float4*)xs;
        for (int idx = g; idx < (64 * I_) / 4; idx += 384) dst[idx] = src[idx];
    }

    float w[I_];
#pragma unroll
    for (int k = 0; k < I_; ++k) w[k] = W_ih[g * I_ + k];
    float bias = b_ih[g];
    __syncthreads();

    for (int r = 0; r < 64; ++r) {
        float acc = bias;
        const float4* row4 = (const float4*)(xs + r * I_);
#pragma unroll
        for (int k4 = 0; k4 < I_ / 4; ++k4) {
            float4 v = row4[k4];   // broadcast across warp: conflict-free
            acc = fmaf(w[4 * k4 + 0], v.x, acc);
            acc = fmaf(w[4 * k4 + 1], v.y, acc);
            acc = fmaf(w[4 * k4 + 2], v.z, acc);
            acc = fmaf(w[4 * k4 + 3], v.w, acc);
        }
        g_xp[(long)(m0 + r) * G_ + g] = acc;  // coalesced over g
    }
}

// ---------------------------------------------------------------------------
// Kernel 3: GRU scan. One CTA per batch element, 384 threads.
// Thread g owns W_hh row g in registers (128 regs). h broadcast from smem.
// gi streamed from g_xp with one-step prefetch. Also does FC head + unscale.
// ---------------------------------------------------------------------------
__global__ __launch_bounds__(384, 1) void gru_kernel(
    const float* __restrict__ W_hh, const float* __restrict__ b_hh,
    const float* __restrict__ W_fc, const float* __restrict__ b_fc,
    float* __restrict__ out) {
    __shared__ float4 sh4[H_ / 4];     // hidden state
    __shared__ float sA[2 * H_];       // r,z pre-activations (gi+gh)
    __shared__ float sGn[H_];          // i_n
    __shared__ float sHn[H_];          // gh_n
    float* sh = (float*)sh4;

    int b = blockIdx.x;
    int g = threadIdx.x;

    float w[H_];
#pragma unroll
    for (int k = 0; k < H_; ++k) w[k] = W_hh[g * H_ + k];
    float bias = b_hh[g];

    if (g < H_) sh[g] = 0.f;

    const float* xpb = g_xp + (long)b * T_ * G_;
    float gi = xpb[g];   // t = 0
    __syncthreads();

    for (int t = 0; t < T_; ++t) {
        // prefetch next step's gi early (hidden under the FFMA loop)
        int tn = (t + 1 < T_) ? (t + 1) : t;
        float gin = xpb[(long)tn * G_ + g];

        float acc = bias;
#pragma unroll
        for (int k4 = 0; k4 < H_ / 4; ++k4) {
            float4 h4 = sh4[k4];      // broadcast: conflict-free LDS.128
            acc = fmaf(w[4 * k4 + 0], h4.x, acc);
            acc = fmaf(w[4 * k4 + 1], h4.y, acc);
            acc = fmaf(w[4 * k4 + 2], h4.z, acc);
            acc = fmaf(w[4 * k4 + 3], h4.w, acc);
        }

        if (g < 2 * H_) {
            sA[g] = gi + acc;                 // r and z pre-activations
        } else {
            sGn[g - 2 * H_] = gi;             // i_n (kept separate!)
            sHn[g - 2 * H_] = acc;            // gh_n
        }
        __syncthreads();

        if (g < H_) {
            float r = sigm_(sA[g]);
            float z = sigm_(sA[H_ + g]);
            float n = tanh_(fmaf(r, sHn[g], sGn[g]));
            sh[g] = (1.f - z) * n + z * sh[g];
        }
        __syncthreads();
        gi = gin;
    }

    if (g < C_) {
        float o = b_fc[g];
        const float* wf = W_fc + g * H_;
#pragma unroll 8
        for (int j = 0; j < H_; ++j) o = fmaf(sh[j], wf[j], o);
        o = (o - BETA_ * g_st12[b * C_ + g]) / (1.f - BETA_);
        o = (o - ALPHA_ * g_st11[b * C_ + g]) / (1.f - ALPHA_);
        out[b * C_ + g] = o;
    }
}

// ---------------------------------------------------------------------------
extern "C" void kernel_launch(void* const* d_in, const int* in_sizes, int n_in,
                              void* d_out, int out_size) {
    const float* x    = (const float*)d_in[0];
    const float* W_ih = (const float*)d_in[1];
    const float* W_hh = (const float*)d_in[2];
    const float* b_ih = (const float*)d_in[3];
    const float* b_hh = (const float*)d_in[4];
    const float* W_fc = (const float*)d_in[5];
    const float* b_fc = (const float*)d_in[6];
    float* out = (float*)d_out;

    ema_kernel<<<B_ * 2, 32>>>(x);
    xp_gemm_kernel<<<(B_ * T_) / 64, 384>>>(W_ih, b_ih);
    gru_kernel<<<B_, 384>>>(W_hh, b_hh, W_fc, b_fc, out);
}

// round 2
// speedup vs baseline: 1.1769x; 1.1769x over previous
#include <cuda_runtime.h>

#define B_ 128
#define T_ 4096
#define I_ 64
#define H_ 128
#define G_ 384   /* 3*H */
#define C_ 2
#define ALPHA_ 0.3f
#define BETA_  0.5f

#define CH_   256   /* EMA chunk length  */
#define HALO_ 64    /* EMA warm-up halo: trunc err ~0.5^64 */

// Scratch (device globals: allocation-free per harness rules)
__device__ float g_x2[(long)B_ * T_ * I_];   // 134 MB: EMA(EMA(x))
__device__ float g_xp[(long)B_ * T_ * G_];   // 805 MB: x2 @ W_ih^T + b_ih
__device__ float g_st11[B_ * C_];
__device__ float g_st12[B_ * C_];

// ---------------- packed f32x2 helpers (sm_100+) ----------------
__device__ __forceinline__ unsigned long long pack2_(float lo, float hi) {
    unsigned long long r;
    asm("mov.b64 %0, {%1, %2};" : "=l"(r) : "f"(lo), "f"(hi));
    return r;
}
__device__ __forceinline__ float2 unpack2_(unsigned long long v) {
    float2 r;
    asm("mov.b64 {%0, %1}, %2;" : "=f"(r.x), "=f"(r.y) : "l"(v));
    return r;
}
__device__ __forceinline__ void fma2_(unsigned long long& d,
                                      unsigned long long a,
                                      unsigned long long b) {
    asm("fma.rn.f32x2 %0, %1, %2, %0;" : "+l"(d) : "l"(a), "l"(b));
}

__device__ __forceinline__ float sigm_(float x) {
    x = fminf(fmaxf(x, -30.f), 30.f);
    return 1.f / (1.f + __expf(-x));
}
__device__ __forceinline__ float tanh_(float x) {
    x = fminf(fmaxf(x, -15.f), 15.f);
    float e = __expf(-2.f * x);
    return (1.f - e) / (1.f + e);
}

// ---------------------------------------------------------------------------
// Kernel 1: chained EMAs, chunked-parallel with decay halo.
// grid = B * (T/CH), block = 64 (one thread per input channel i).
// Chunk c warms up from t0-HALO with x1=x2=x[t0-HALO]; error decays 0.5^HALO.
// ---------------------------------------------------------------------------
__global__ __launch_bounds__(64) void ema_kernel(const float* __restrict__ x) {
    int nchunk = T_ / CH_;
    int c = blockIdx.x % nchunk;
    int b = blockIdx.x / nchunk;
    int i = threadIdx.x;

    const float* xin = x + (long)b * T_ * I_ + i;
    float* o = g_x2 + (long)b * T_ * I_ + i;

    int t0 = c * CH_;
    int ts = (c == 0) ? 0 : (t0 - HALO_);

    float x1 = xin[(long)ts * I_];
    float x2 = x1;

    // halo warm-up (no stores)
#pragma unroll 4
    for (int t = ts + 1; t < t0; ++t) {
        float xt = xin[(long)t * I_];
        x1 = fmaf(ALPHA_, x1, (1.f - ALPHA_) * xt);
        x2 = fmaf(BETA_, x2, (1.f - BETA_) * x1);
    }

    if (c == 0) o[0] = x2;           // t = 0 output (exact init)
    int tb = (c == 0) ? 1 : t0;
#pragma unroll 4
    for (int t = tb; t < t0 + CH_; ++t) {
        float xt = xin[(long)t * I_];
        x1 = fmaf(ALPHA_, x1, (1.f - ALPHA_) * xt);
        x2 = fmaf(BETA_, x2, (1.f - BETA_) * x1);
        o[(long)t * I_] = x2;
    }

    if (c == nchunk - 1 && (i == 1 || i == 2)) {
        g_st11[b * C_ + (i - 1)] = x1;
        g_st12[b * C_ + (i - 1)] = x2;
    }
}

// ---------------------------------------------------------------------------
// Kernel 2: xp[m, g] = b_ih[g] + sum_k x2[m, k] * W_ih[g, k]   (f32x2 packed)
// One CTA = 64 rows x 384 cols.
// ---------------------------------------------------------------------------
__global__ __launch_bounds__(384) void xp_gemm_kernel(
    const float* __restrict__ W_ih, const float* __restrict__ b_ih) {
    __shared__ __align__(16) float xs[64 * I_];  // 16 KB
    int m0 = blockIdx.x * 64;
    int g = threadIdx.x;

    {
        const float4* src = (const float4*)(g_x2 + (long)m0 * I_);
        float4* dst = (float4*)xs;
        for (int idx = g; idx < (64 * I_) / 4; idx += 384) dst[idx] = src[idx];
    }

    // W_ih row packed as 32 f32x2 pairs (memory order == lane order)
    unsigned long long w2[I_ / 2];
    {
        const unsigned long long* wrow =
            (const unsigned long long*)(W_ih + g * I_);
#pragma unroll
        for (int k = 0; k < I_ / 2; ++k) w2[k] = wrow[k];
    }
    float bias = b_ih[g];
    __syncthreads();

    for (int r = 0; r < 64; ++r) {
        unsigned long long acc0 = pack2_(bias, 0.f);
        unsigned long long acc1 = pack2_(0.f, 0.f);
        const ulonglong2* row8 = (const ulonglong2*)(xs + r * I_);
#pragma unroll
        for (int k = 0; k < I_ / 4; ++k) {
            ulonglong2 v = row8[k];          // LDS.128, warp-broadcast
            fma2_(acc0, w2[2 * k + 0], v.x);
            fma2_(acc1, w2[2 * k + 1], v.y);
        }
        float2 a0 = unpack2_(acc0);
        float2 a1 = unpack2_(acc1);
        g_xp[(long)(m0 + r) * G_ + g] = (a0.x + a1.x) + (a0.y + a1.y);
    }
}

// ---------------------------------------------------------------------------
// Kernel 3: GRU scan. One CTA per batch element, 384 threads.
// Thread g owns W_hh row g packed as 64 f32x2 pairs in registers.
// ---------------------------------------------------------------------------
__global__ __launch_bounds__(384, 1) void gru_kernel(
    const float* __restrict__ W_hh, const float* __restrict__ b_hh,
    const float* __restrict__ W_fc, const float* __restrict__ b_fc,
    float* __restrict__ out) {
    __shared__ __align__(16) float sh[H_];   // hidden state
    __shared__ float sA[2 * H_];             // r,z pre-activations (gi+gh)
    __shared__ float sGn[H_];                // i_n
    __shared__ float sHn[H_];                // gh_n

    int b = blockIdx.x;
    int g = threadIdx.x;

    unsigned long long w2[H_ / 2];
    {
        const unsigned long long* wrow =
            (const unsigned long long*)(W_hh + g * H_);
#pragma unroll
        for (int k = 0; k < H_ / 2; ++k) w2[k] = wrow[k];
    }
    float bias = b_hh[g];

    if (g < H_) sh[g] = 0.f;

    const float* xpb = g_xp + (long)b * T_ * G_;
    float gi = xpb[g];   // t = 0
    __syncthreads();

    for (int t = 0; t < T_; ++t) {
        // prefetch next step's gi (hidden under the FMA loop)
        int tn = (t + 1 < T_) ? (t + 1) : t;
        float gin = xpb[(long)tn * G_ + g];

        unsigned long long acc0 = pack2_(bias, 0.f);
        unsigned long long acc1 = pack2_(0.f, 0.f);
        const ulonglong2* h8 = (const ulonglong2*)sh;
#pragma unroll
        for (int k = 0; k < H_ / 4; ++k) {
            ulonglong2 hv = h8[k];           // LDS.128, warp-broadcast
            fma2_(acc0, w2[2 * k + 0], hv.x);
            fma2_(acc1, w2[2 * k + 1], hv.y);
        }
        float2 a0 = unpack2_(acc0);
        float2 a1 = unpack2_(acc1);
        float acc = (a0.x + a1.x) + (a0.y + a1.y);

        if (g < 2 * H_) {
            sA[g] = gi + acc;                // r and z pre-activations
        } else {
            sGn[g - 2 * H_] = gi;            // i_n
            sHn[g - 2 * H_] = acc;           // gh_n
        }
        __syncthreads();

        if (g < H_) {
            float r = sigm_(sA[g]);
            float z = sigm_(sA[H_ + g]);
            float n = tanh_(fmaf(r, sHn[g], sGn[g]));
            sh[g] = (1.f - z) * n + z * sh[g];
        }
        __syncthreads();
        gi = gin;
    }

    if (g < C_) {
        float o = b_fc[g];
        const float* wf = W_fc + g * H_;
#pragma unroll 8
        for (int j = 0; j < H_; ++j) o = fmaf(sh[j], wf[j], o);
        o = (o - BETA_ * g_st12[b * C_ + g]) / (1.f - BETA_);
        o = (o - ALPHA_ * g_st11[b * C_ + g]) / (1.f - ALPHA_);
        out[b * C_ + g] = o;
    }
}

// ---------------------------------------------------------------------------
extern "C" void kernel_launch(void* const* d_in, const int* in_sizes, int n_in,
                              void* d_out, int out_size) {
    const float* x    = (const float*)d_in[0];
    const float* W_ih = (const float*)d_in[1];
    const float* W_hh = (const float*)d_in[2];
    const float* b_ih = (const float*)d_in[3];
    const float* b_hh = (const float*)d_in[4];
    const float* W_fc = (const float*)d_in[5];
    const float* b_fc = (const float*)d_in[6];
    float* out = (float*)d_out;

    ema_kernel<<<B_ * (T_ / CH_), 64>>>(x);
    xp_gemm_kernel<<<(B_ * T_) / 64, 384>>>(W_ih, b_ih);
    gru_kernel<<<B_, 384>>>(W_hh, b_hh, W_fc, b_fc, out);
}